// round 2
// baseline (speedup 1.0000x reference)
#include <cuda_runtime.h>
#include <cstdint>

#define Bb 16
#define Nn 25200
#define NCc 80
#define KC 1024
#define MAXD 300
#define CONF_T 0.4f
#define IOU_T 0.25f
#define CAP 2048
#define APB 128   // anchors per block in k1

// ---------------- scratch (static device globals; no allocation) ----------------
__device__ float    g_conf[Bb * Nn];     // masked conf (-1 if not candidate)
__device__ int      g_cls [Bb * Nn];     // argmax class
__device__ float4   g_box [Bb * KC];     // selected boxes xyxy (sorted by conf desc)
__device__ float    g_cconf[Bb * KC];    // selected conf (0 if slot invalid)
__device__ int      g_ccls[Bb * KC];     // selected class
__device__ unsigned g_mask[Bb * 32 * KC];// [b][chunk c][col j]: bit i = iou(32c+i, j)>thr && (32c+i)<j

// ---------------- kernel 1: per-anchor conf/argmax (smem-staged, coalesced) ----------------
__global__ __launch_bounds__(APB) void k1_scores(const float* __restrict__ pred) {
    __shared__ float s[APB * 85];
    int t = threadIdx.x;
    // coalesced float4 stage-in: 128 anchors * 85 floats = 2720 float4
    const float4* src = (const float4*)(pred + (size_t)blockIdx.x * (APB * 85));
    float4* dst = (float4*)s;
    #pragma unroll 4
    for (int i = t; i < APB * 85 / 4; i += APB) dst[i] = src[i];
    __syncthreads();

    const float* p = s + t * 85;   // stride 85: gcd(85,32)=1 -> conflict-free LDS
    float obj = p[4];
    float m = -1e30f; int arg = 0;
    #pragma unroll
    for (int c = 0; c < NCc; c++) {
        float sc = p[5 + c] * obj;            // exact reference op order
        if (sc > m) { m = sc; arg = c; }      // first-max semantics
    }
    bool cand = (obj > CONF_T) && (m > CONF_T);
    int idx = blockIdx.x * APB + t;
    g_conf[idx] = cand ? m : -1.0f;
    g_cls[idx]  = arg;
}

// ---------------- kernel 2: per-batch exact top-1024 (hist-select + bitonic sort) ----------------
__global__ __launch_bounds__(1024) void k2_select(const float* __restrict__ pred) {
    __shared__ unsigned hist[256];
    __shared__ unsigned long long skeys[CAP];
    __shared__ unsigned scnt;
    __shared__ int sB1;
    int b = blockIdx.x, tid = threadIdx.x;
    if (tid < 256) hist[tid] = 0u;
    if (tid == 0) scnt = 0u;
    __syncthreads();

    const float* cf = g_conf + b * Nn;
    for (int n = tid; n < Nn; n += 1024) {
        float c = cf[n];
        if (c > CONF_T) {
            unsigned bits = __float_as_uint(c);
            int bk = (int)(bits >> 16) - 0x3ECC;     // conf>0.4 -> monotone bucket
            bk = max(0, min(255, bk));
            atomicAdd(&hist[bk], 1u);
        }
    }
    __syncthreads();
    if (tid == 0) {
        unsigned cum = 0; int bsel = 0; bool found = false;
        for (int kk = 255; kk >= 0; kk--) {
            cum += hist[kk];
            if (cum >= KC) { bsel = kk; found = true; break; }
        }
        sB1 = found ? bsel : 0;
    }
    __syncthreads();
    int B1 = sB1;
    for (int n = tid; n < Nn; n += 1024) {
        float c = cf[n];
        if (c > CONF_T) {
            unsigned bits = __float_as_uint(c);
            int bk = (int)(bits >> 16) - 0x3ECC;
            bk = max(0, min(255, bk));
            if (bk >= B1) {
                unsigned pos = atomicAdd(&scnt, 1u);
                if (pos < CAP)
                    skeys[pos] = ((unsigned long long)bits << 32) | (unsigned)(~n);
            }
        }
    }
    __syncthreads();
    unsigned tot = min(scnt, (unsigned)CAP);
    for (int i = tid; i < CAP; i += 1024)
        if ((unsigned)i >= tot) skeys[i] = 0ull;

    // bitonic sort, descending; ties break to smaller index via ~n low bits
    for (int k = 2; k <= CAP; k <<= 1) {
        for (int jj = k >> 1; jj > 0; jj >>= 1) {
            __syncthreads();
            for (int i = tid; i < CAP; i += 1024) {
                int ixj = i ^ jj;
                if (ixj > i) {
                    unsigned long long a = skeys[i], bb = skeys[ixj];
                    bool up = (i & k) == 0;
                    if (up ? (a < bb) : (a > bb)) { skeys[i] = bb; skeys[ixj] = a; }
                }
            }
        }
    }
    __syncthreads();

    // extract top KC, convert boxes xywh->xyxy
    unsigned long long key = skeys[tid];
    unsigned bits = (unsigned)(key >> 32);
    int n = (int)(~(unsigned)(key & 0xFFFFFFFFull));
    float conf = __uint_as_float(bits);
    float4 bx = make_float4(0.f, 0.f, 0.f, 0.f);
    int cls = 0;
    if (conf > CONF_T) {
        const float* p = pred + ((size_t)b * Nn + n) * 85;
        float cx = p[0], cy = p[1], w = p[2], h = p[3];
        bx.x = cx - w * 0.5f; bx.y = cy - h * 0.5f;
        bx.z = cx + w * 0.5f; bx.w = cy + h * 0.5f;
        cls = g_cls[b * Nn + n];
    } else {
        conf = 0.0f;
    }
    g_box  [b * KC + tid] = bx;
    g_cconf[b * KC + tid] = conf;
    g_ccls [b * KC + tid] = cls;
}

// ---------------- kernel 3: IoU suppression bit-matrix (chip-wide parallel) ----------------
__global__ __launch_bounds__(1024) void k3_iou() {
    int c = blockIdx.x;   // row chunk (0..31)
    int b = blockIdx.y;   // batch
    int j = threadIdx.x;  // column
    __shared__ float4 rbx[32];
    __shared__ float rarea[32];
    if (j < 32) {
        float4 v = g_box[b * KC + c * 32 + j];
        rbx[j] = v;
        rarea[j] = (v.z - v.x) * (v.w - v.y);
    }
    __syncthreads();
    unsigned word = 0;
    if (j > c * 32) {                  // only rows i < j can suppress column j
        float4 bj = g_box[b * KC + j];
        float aj = (bj.z - bj.x) * (bj.w - bj.y);
        int lim = min(32, j - c * 32);
        for (int i = 0; i < lim; i++) {
            float4 ri = rbx[i];
            float ltx = fmaxf(ri.x, bj.x), lty = fmaxf(ri.y, bj.y);
            float rx  = fminf(ri.z, bj.z), ry  = fminf(ri.w, bj.w);
            float w = fmaxf(rx - ltx, 0.f), h = fmaxf(ry - lty, 0.f);
            float inter = w * h;
            float iou = inter / (rarea[i] + aj - inter + 1e-9f);
            if (iou > IOU_T) word |= (1u << i);
        }
    }
    g_mask[(b * 32 + c) * KC + j] = word;
}

// ---------------- kernel 4: greedy NMS (warp turn-chain) + output assembly ----------------
__global__ __launch_bounds__(1024) void k4_nms(const int* __restrict__ pimg,
                                               float* __restrict__ out) {
    int b = blockIdx.x, j = threadIdx.x;
    int lane = j & 31, warp = j >> 5;
    float conf = g_cconf[b * KC + j];
    bool alive = conf > CONF_T;            // valid0

    unsigned w[32];
    #pragma unroll
    for (int c = 0; c < 32; c++) w[c] = g_mask[(b * 32 + c) * KC + j];

    __shared__ volatile unsigned skept[32];
    __shared__ volatile int turn;
    __shared__ unsigned keptall[32];
    __shared__ int snk;
    if (j == 0) turn = 0;
    __syncthreads();

    // wait for my turn in the greedy chain
    if (lane == 0) { while (turn < warp) { } }
    __syncwarp();
    __threadfence_block();

    // fold in suppression from all earlier (already-resolved) chunks
    #pragma unroll
    for (int c = 0; c < 32; c++)
        if (c < warp) alive = alive && !(w[c] & skept[c]);

    // greedy resolve within my own 32-item chunk
    {
        unsigned rem = __ballot_sync(0xffffffffu, alive);
        unsigned W = w[warp];              // bits: rows i<j in my chunk that suppress col j
        unsigned kept = 0;
        while (rem) {
            int bs = __ffs(rem) - 1;
            kept |= (1u << bs);
            unsigned row = __ballot_sync(0xffffffffu, (W >> bs) & 1u);
            rem &= ~(1u << bs) & ~row;
        }
        alive = alive && ((kept >> lane) & 1u);
        if (lane == 0) {
            skept[warp] = kept;
            __threadfence_block();
            turn = warp + 1;               // release next warp
        }
    }
    __syncthreads();

    unsigned ab = __ballot_sync(0xffffffffu, alive);
    if (lane == 0) keptall[warp] = ab;
    __syncthreads();
    if (j == 0) {
        int s = 0;
        for (int ww = 0; ww < 32; ww++) s += __popc(keptall[ww]);
        snk = s;
    }
    __syncthreads();
    int nk = snk;
    int rank = 0;
    for (int ww = 0; ww < warp; ww++) rank += __popc(keptall[ww]);
    rank += __popc(keptall[warp] & ((1u << lane) - 1u));

    // output layout: dets[16*300*6] | valid[16*300] | feats[300*82]
    float* dets  = out;
    float* valid = out + Bb * MAXD * 6;
    float* feats = out + Bb * MAXD * 6 + Bb * MAXD;

    float fimg = 640.0f;
    if (pimg) {
        int iv = *pimg;
        fimg = (iv > 0 && iv < (1 << 20)) ? (float)iv : __int_as_float(iv);
    }
    float scale = 1.0f / fimg;

    for (int r = j; r < MAXD; r += 1024) {
        bool v = r < nk;
        if (!v) {
            #pragma unroll
            for (int q = 0; q < 6; q++) dets[((size_t)b * MAXD + r) * 6 + q] = 0.f;
        }
        valid[b * MAXD + r] = v ? 1.0f : 0.0f;
    }
    if (b == 0) {
        for (int i = j; i < MAXD * (NCc + 2); i += 1024) feats[i] = 0.f;
    }
    __syncthreads();

    // kept items: rank r < 300 written (kept-first stable order == index order)
    if (alive && rank < MAXD) {
        float4 bx = g_box[b * KC + j];
        int cls = g_ccls[b * KC + j];
        float* dr = dets + ((size_t)b * MAXD + rank) * 6;
        dr[0] = bx.x; dr[1] = bx.y; dr[2] = bx.z; dr[3] = bx.w;
        dr[4] = conf; dr[5] = (float)cls;
        if (b == 0) {
            float cx = (bx.x + bx.z) * 0.5f * scale;
            float cy = (bx.y + bx.w) * 0.5f * scale;
            feats[rank * (NCc + 2) + 0] = cx;
            feats[rank * (NCc + 2) + 1] = cy;
            feats[rank * (NCc + 2) + 2 + cls] = 1.0f;
        }
    }
}

// ---------------- launch ----------------
extern "C" void kernel_launch(void* const* d_in, const int* in_sizes, int n_in,
                              void* d_out, int out_size) {
    const float* pred = (const float*)d_in[0];
    const int* pimg = (n_in >= 2) ? (const int*)d_in[1] : nullptr;
    float* out = (float*)d_out;

    k1_scores<<<(Bb * Nn) / APB, APB>>>(pred);
    k2_select<<<Bb, 1024>>>(pred);
    k3_iou<<<dim3(32, Bb), 1024>>>();
    k4_nms<<<Bb, 1024>>>(pimg, out);
}

// round 3
// speedup vs baseline: 1.2538x; 1.2538x over previous
#include <cuda_runtime.h>
#include <cstdint>

#define Bb 16
#define Nn 25200
#define NCc 80
#define KC 1024
#define MAXD 300
#define CONF_T 0.4f
#define IOU_T 0.25f
#define CAP 2048
#define APB 128   // anchors per block in k1

// ---------------- scratch (static device globals; no allocation) ----------------
__device__ float    g_conf[Bb * Nn];      // masked conf (-1 if not candidate)
__device__ int      g_cls [Bb * Nn];      // argmax class
__device__ unsigned g_hist[Bb * 256];     // per-batch conf histogram (built in k1)
__device__ float4   g_box [Bb * KC];      // selected boxes xyxy (sorted by conf desc)
__device__ float    g_cconf[Bb * KC];     // selected conf (0 if slot invalid)
__device__ int      g_ccls[Bb * KC];      // selected class
__device__ unsigned g_mask[Bb * 32 * KC]; // [b][chunk c][col j]: bit i = iou(32c+i,j)>thr && 32c+i<j

// ---------------- kernel 0: zero histograms (graph replays need re-zero) ----------------
__global__ void k0_zero() {
    int i = blockIdx.x * blockDim.x + threadIdx.x;
    if (i < Bb * 256) g_hist[i] = 0u;
}

// ---------------- kernel 1: per-anchor conf/argmax (smem-staged) + histogram ----------------
__global__ __launch_bounds__(APB) void k1_scores(const float* __restrict__ pred) {
    __shared__ float s[APB * 85];
    int t = threadIdx.x;
    const float4* src = (const float4*)(pred + (size_t)blockIdx.x * (APB * 85));
    float4* dst = (float4*)s;
    #pragma unroll 4
    for (int i = t; i < APB * 85 / 4; i += APB) dst[i] = src[i];
    __syncthreads();

    const float* p = s + t * 85;   // stride 85: gcd(85,32)=1 -> conflict-free LDS
    float obj = p[4];
    float m = -1e30f; int arg = 0;
    #pragma unroll
    for (int c = 0; c < NCc; c++) {
        float sc = p[5 + c] * obj;            // exact reference op order
        if (sc > m) { m = sc; arg = c; }      // first-max semantics
    }
    bool cand = (obj > CONF_T) && (m > CONF_T);
    int idx = blockIdx.x * APB + t;
    int b = idx / Nn;
    g_conf[idx] = cand ? m : -1.0f;
    g_cls[idx]  = arg;
    if (cand) {
        unsigned bits = __float_as_uint(m);
        int bk = (int)(bits >> 16) - 0x3ECC;  // conf>0.4 -> bk in [0,179]
        bk = max(0, min(255, bk));
        atomicAdd(&g_hist[b * 256 + bk], 1u);
    }
}

// ---------------- kernel 2: per-batch exact top-1024 (threshold + gather + bitonic) ----------------
__global__ __launch_bounds__(1024) void k2_select(const float* __restrict__ pred) {
    __shared__ unsigned long long skeys[CAP];
    __shared__ unsigned scnt;
    __shared__ int sB1;
    int b = blockIdx.x, tid = threadIdx.x;
    if (tid == 0) {
        scnt = 0u;
        unsigned cum = 0; int bsel = 0;
        for (int kk = 255; kk >= 0; kk--) {
            cum += g_hist[b * 256 + kk];
            if (cum >= KC) { bsel = kk; break; }
        }
        sB1 = bsel;
    }
    __syncthreads();
    int B1 = sB1;

    const float* cf = g_conf + b * Nn;
    for (int n = tid; n < Nn; n += 1024) {
        float c = cf[n];
        if (c > CONF_T) {
            unsigned bits = __float_as_uint(c);
            int bk = (int)(bits >> 16) - 0x3ECC;
            bk = max(0, min(255, bk));
            if (bk >= B1) {
                unsigned pos = atomicAdd(&scnt, 1u);
                if (pos < CAP)
                    skeys[pos] = ((unsigned long long)bits << 32) | (unsigned)(~n);
            }
        }
    }
    __syncthreads();
    unsigned tot = min(scnt, (unsigned)CAP);
    for (int i = tid; i < CAP; i += 1024)
        if ((unsigned)i >= tot) skeys[i] = 0ull;

    // bitonic sort, descending; ties break to smaller index via ~n low bits
    for (int k = 2; k <= CAP; k <<= 1) {
        for (int jj = k >> 1; jj > 0; jj >>= 1) {
            __syncthreads();
            for (int i = tid; i < CAP; i += 1024) {
                int ixj = i ^ jj;
                if (ixj > i) {
                    unsigned long long a = skeys[i], bb = skeys[ixj];
                    bool up = (i & k) == 0;
                    if (up ? (a < bb) : (a > bb)) { skeys[i] = bb; skeys[ixj] = a; }
                }
            }
        }
    }
    __syncthreads();

    // extract top KC, convert boxes xywh->xyxy
    unsigned long long key = skeys[tid];
    unsigned bits = (unsigned)(key >> 32);
    int n = (int)(~(unsigned)(key & 0xFFFFFFFFull));
    float conf = __uint_as_float(bits);
    float4 bx = make_float4(0.f, 0.f, 0.f, 0.f);
    int cls = 0;
    if (conf > CONF_T) {
        const float* p = pred + ((size_t)b * Nn + n) * 85;
        float cx = p[0], cy = p[1], w = p[2], h = p[3];
        bx.x = cx - w * 0.5f; bx.y = cy - h * 0.5f;
        bx.z = cx + w * 0.5f; bx.w = cy + h * 0.5f;
        cls = g_cls[b * Nn + n];
    } else {
        conf = 0.0f;
    }
    g_box  [b * KC + tid] = bx;
    g_cconf[b * KC + tid] = conf;
    g_ccls [b * KC + tid] = cls;
}

// ---------------- kernel 3: IoU suppression bit-matrix (chip-wide parallel) ----------------
__global__ __launch_bounds__(1024) void k3_iou() {
    int c = blockIdx.x;   // row chunk (0..31)
    int b = blockIdx.y;   // batch
    int j = threadIdx.x;  // column
    __shared__ float4 rbx[32];
    __shared__ float rarea[32];
    if (j < 32) {
        float4 v = g_box[b * KC + c * 32 + j];
        rbx[j] = v;
        rarea[j] = (v.z - v.x) * (v.w - v.y);
    }
    __syncthreads();
    unsigned word = 0;
    if (j > c * 32) {                  // only rows i < j can suppress column j
        float4 bj = g_box[b * KC + j];
        float aj = (bj.z - bj.x) * (bj.w - bj.y);
        int lim = min(32, j - c * 32);
        for (int i = 0; i < lim; i++) {
            float4 ri = rbx[i];
            float ltx = fmaxf(ri.x, bj.x), lty = fmaxf(ri.y, bj.y);
            float rx  = fminf(ri.z, bj.z), ry  = fminf(ri.w, bj.w);
            float w = fmaxf(rx - ltx, 0.f), h = fmaxf(ry - lty, 0.f);
            float inter = w * h;
            float iou = inter / (rarea[i] + aj - inter + 1e-9f);
            if (iou > IOU_T) word |= (1u << i);
        }
    }
    g_mask[(b * 32 + c) * KC + j] = word;
}

// ---------------- kernel 4: greedy NMS (1 barrier per chunk) + output assembly ----------------
__global__ __launch_bounds__(1024) void k4_nms(const int* __restrict__ pimg,
                                               float* __restrict__ out) {
    int b = blockIdx.x, j = threadIdx.x;
    int lane = j & 31, warp = j >> 5;
    float conf = g_cconf[b * KC + j];
    bool alive = conf > CONF_T;            // valid0

    unsigned w[32];
    #pragma unroll
    for (int c = 0; c < 32; c++) w[c] = g_mask[(b * 32 + c) * KC + j];

    __shared__ unsigned skept[32];
    __shared__ unsigned keptall[32];
    __shared__ int snk;

    // pipeline: at iter c, apply chunk c-1's kept mask, then warp c resolves its chunk
    #pragma unroll 1
    for (int c = 0; c < 32; c++) {
        if (c > 0 && warp >= c) alive = alive && !(w[c - 1] & skept[c - 1]);
        if (warp == c) {
            unsigned rem = __ballot_sync(0xffffffffu, alive);
            unsigned W = w[c];             // bits: rows i<j in my chunk that suppress col j
            unsigned kept = 0;
            while (rem) {
                int bs = __ffs(rem) - 1;
                kept |= (1u << bs);
                unsigned row = __ballot_sync(0xffffffffu, (W >> bs) & 1u);
                rem &= ~(1u << bs) & ~row;
            }
            alive = alive && ((kept >> lane) & 1u);
            if (lane == 0) skept[c] = kept;
        }
        __syncthreads();
    }

    unsigned ab = __ballot_sync(0xffffffffu, alive);
    if (lane == 0) keptall[warp] = ab;
    __syncthreads();
    if (j == 0) {
        int s = 0;
        for (int ww = 0; ww < 32; ww++) s += __popc(keptall[ww]);
        snk = s;
    }
    __syncthreads();
    int nk = snk;
    int rank = 0;
    for (int ww = 0; ww < warp; ww++) rank += __popc(keptall[ww]);
    rank += __popc(keptall[warp] & ((1u << lane) - 1u));

    // output layout: dets[16*300*6] | valid[16*300] | feats[300*82]
    float* dets  = out;
    float* valid = out + Bb * MAXD * 6;
    float* feats = out + Bb * MAXD * 6 + Bb * MAXD;

    float fimg = 640.0f;
    if (pimg) {
        int iv = *pimg;
        fimg = (iv > 0 && iv < (1 << 20)) ? (float)iv : __int_as_float(iv);
    }
    float scale = 1.0f / fimg;

    for (int r = j; r < MAXD; r += 1024) {
        bool v = r < nk;
        if (!v) {
            #pragma unroll
            for (int q = 0; q < 6; q++) dets[((size_t)b * MAXD + r) * 6 + q] = 0.f;
        }
        valid[b * MAXD + r] = v ? 1.0f : 0.0f;
    }
    if (b == 0) {
        for (int i = j; i < MAXD * (NCc + 2); i += 1024) feats[i] = 0.f;
    }
    __syncthreads();

    // kept items: rank r < 300 written (kept-first stable order == index order)
    if (alive && rank < MAXD) {
        float4 bx = g_box[b * KC + j];
        int cls = g_ccls[b * KC + j];
        float* dr = dets + ((size_t)b * MAXD + rank) * 6;
        dr[0] = bx.x; dr[1] = bx.y; dr[2] = bx.z; dr[3] = bx.w;
        dr[4] = conf; dr[5] = (float)cls;
        if (b == 0) {
            float cx = (bx.x + bx.z) * 0.5f * scale;
            float cy = (bx.y + bx.w) * 0.5f * scale;
            feats[rank * (NCc + 2) + 0] = cx;
            feats[rank * (NCc + 2) + 1] = cy;
            feats[rank * (NCc + 2) + 2 + cls] = 1.0f;
        }
    }
}

// ---------------- launch ----------------
extern "C" void kernel_launch(void* const* d_in, const int* in_sizes, int n_in,
                              void* d_out, int out_size) {
    const float* pred = (const float*)d_in[0];
    const int* pimg = (n_in >= 2) ? (const int*)d_in[1] : nullptr;
    float* out = (float*)d_out;

    k0_zero<<<(Bb * 256 + 255) / 256, 256>>>();
    k1_scores<<<(Bb * Nn) / APB, APB>>>(pred);
    k2_select<<<Bb, 1024>>>(pred);
    k3_iou<<<dim3(32, Bb), 1024>>>();
    k4_nms<<<Bb, 1024>>>(pimg, out);
}